// round 1
// baseline (speedup 1.0000x reference)
#include <cuda_runtime.h>

// Problem constants
#define NH 12
#define HD 64
#define CD 768
#define LS 1024
#define BATCH 4
#define ML (BATCH*LS)      // 4096 token rows
#define ATT_SCALE 0.125f   // HEAD_DIM^-0.5

// Scratch (device globals: allocation-free rule)
__device__ float g_q[ML*CD];   // [B,H,L,D]
__device__ float g_k[ML*CD];   // [B,H,L,D]
__device__ float g_v[ML*CD];   // [B,H,L,D]
__device__ float g_o[ML*CD];   // [B,L,C]

// ---------------------------------------------------------------------------
// Fused QKV projection.
// out[m,n] = sum_k (x[m,k] + ape[l,k]) * W[n,k]   (W row-major [N,K], NT GEMM)
// Tile: BM=128, BN=64, BK=16. 256 threads, 8x4 outputs/thread.
// blockIdx.z selects q/k/v. Output written in [B,H,L,D] layout.
// ---------------------------------------------------------------------------
__global__ __launch_bounds__(256) void qkv_kernel(
    const float* __restrict__ x,
    const float* __restrict__ qape,
    const float* __restrict__ kape,
    const float* __restrict__ Wq,
    const float* __restrict__ Wk,
    const float* __restrict__ Wv)
{
    __shared__ float As[16][128];
    __shared__ float Bs[16][64];

    const int which = blockIdx.z;
    const float* ape = (which == 0) ? qape : (which == 1) ? kape : nullptr;
    const float* W   = (which == 0) ? Wq   : (which == 1) ? Wk   : Wv;
    float* out       = (which == 0) ? g_q  : (which == 1) ? g_k  : g_v;

    const int tid = threadIdx.x;
    const int m0 = blockIdx.y * 128;
    const int n0 = blockIdx.x * 64;

    const int ar = tid >> 2;          // 0..63 (row within tile / weight row)
    const int ac = (tid & 3) << 2;    // 0,4,8,12 (k offset)
    const int ty = tid >> 4;          // 0..15 -> 8 m-rows
    const int tx = tid & 15;          // 0..15 -> 4 n-cols

    const int m1 = m0 + ar;
    const int m2 = m0 + ar + 64;
    const int l1 = m1 & (LS - 1);
    const int l2 = m2 & (LS - 1);

    float acc[8][4];
#pragma unroll
    for (int i = 0; i < 8; i++)
#pragma unroll
        for (int j = 0; j < 4; j++) acc[i][j] = 0.f;

    for (int k0 = 0; k0 < CD; k0 += 16) {
        float4 a0 = *(const float4*)(x + (size_t)m1 * CD + k0 + ac);
        float4 a1 = *(const float4*)(x + (size_t)m2 * CD + k0 + ac);
        if (ape) {
            float4 p0 = *(const float4*)(ape + (size_t)l1 * CD + k0 + ac);
            float4 p1 = *(const float4*)(ape + (size_t)l2 * CD + k0 + ac);
            a0.x += p0.x; a0.y += p0.y; a0.z += p0.z; a0.w += p0.w;
            a1.x += p1.x; a1.y += p1.y; a1.z += p1.z; a1.w += p1.w;
        }
        float4 b0 = *(const float4*)(W + (size_t)(n0 + ar) * CD + k0 + ac);

        As[ac + 0][ar] = a0.x; As[ac + 1][ar] = a0.y;
        As[ac + 2][ar] = a0.z; As[ac + 3][ar] = a0.w;
        As[ac + 0][ar + 64] = a1.x; As[ac + 1][ar + 64] = a1.y;
        As[ac + 2][ar + 64] = a1.z; As[ac + 3][ar + 64] = a1.w;
        Bs[ac + 0][ar] = b0.x; Bs[ac + 1][ar] = b0.y;
        Bs[ac + 2][ar] = b0.z; Bs[ac + 3][ar] = b0.w;
        __syncthreads();

#pragma unroll
        for (int kk = 0; kk < 16; kk++) {
            float af[8], bf[4];
            *(float4*)(af)     = *(const float4*)&As[kk][ty * 8];
            *(float4*)(af + 4) = *(const float4*)&As[kk][ty * 8 + 4];
            *(float4*)(bf)     = *(const float4*)&Bs[kk][tx * 4];
#pragma unroll
            for (int i = 0; i < 8; i++)
#pragma unroll
                for (int j = 0; j < 4; j++)
                    acc[i][j] = fmaf(af[i], bf[j], acc[i][j]);
        }
        __syncthreads();
    }

    // Epilogue: n0 is 64-aligned so the whole block lives inside one head.
    const int h = n0 >> 6;
    const int d = tx * 4;
#pragma unroll
    for (int i = 0; i < 8; i++) {
        int m = m0 + ty * 8 + i;
        int b = m >> 10;
        int l = m & (LS - 1);
        float4 v = make_float4(acc[i][0], acc[i][1], acc[i][2], acc[i][3]);
        *(float4*)(out + ((size_t)((b * NH + h) * LS + l)) * HD + d) = v;
    }
}

// ---------------------------------------------------------------------------
// Flash-style attention per (b,h), 64-query x 64-key tiles, HD=64.
// Q tile resident; K stored transposed Kt[d][k] for conflict-free LDS.128;
// P tile reuses the Kt buffer (as P[q][k]) between the S and PV phases.
// Online softmax with half-warp (width-16) shuffles.
// Writes g_o in [B,L,C] layout for the projection GEMM.
// ---------------------------------------------------------------------------
__global__ __launch_bounds__(256) void attn_kernel(const float* __restrict__ pos)
{
    __shared__ float Qs[64][64];
    __shared__ float Kt[64][64];   // K^T during S phase, P[q][k] during PV phase
    __shared__ float Vs[64][64];

    const int tid = threadIdx.x;
    const int bh  = blockIdx.y;
    const int b   = bh / NH;
    const int h   = bh - b * NH;
    const int q0  = blockIdx.x * 64;

    const int ty = tid >> 4;         // 0..15 -> 4 q rows
    const int tx = tid & 15;         // 0..15 -> 4 kv/d cols
    const int r  = tid >> 2;         // 0..63 loader row
    const int sc = (tid & 3) << 4;   // 0,16,32,48 loader col segment

    const float* qb = g_q + ((size_t)bh * LS + q0) * HD;
    const float* kb = g_k + (size_t)bh * LS * HD;
    const float* vb = g_v + (size_t)bh * LS * HD;
    const float* pb = pos + ((size_t)h * LS + q0) * LS;

    // Load Q tile (coalesced)
#pragma unroll
    for (int u = 0; u < 4; u++)
        *(float4*)&Qs[r][sc + u * 4] = *(const float4*)(qb + (size_t)r * HD + sc + u * 4);

    float mi[4], li[4], o[4][4];
#pragma unroll
    for (int i = 0; i < 4; i++) {
        mi[i] = -1e30f; li[i] = 0.f;
#pragma unroll
        for (int j = 0; j < 4; j++) o[i][j] = 0.f;
    }

    for (int j0 = 0; j0 < LS; j0 += 64) {
        __syncthreads();  // protect Qs(first iter) / Kt,Vs(prev iter) before overwrite
        // Load K (transposed into Kt) and V
#pragma unroll
        for (int u = 0; u < 4; u++) {
            float4 kv = *(const float4*)(kb + (size_t)(j0 + r) * HD + sc + u * 4);
            Kt[sc + u * 4 + 0][r] = kv.x;
            Kt[sc + u * 4 + 1][r] = kv.y;
            Kt[sc + u * 4 + 2][r] = kv.z;
            Kt[sc + u * 4 + 3][r] = kv.w;
            *(float4*)&Vs[r][sc + u * 4] =
                *(const float4*)(vb + (size_t)(j0 + r) * HD + sc + u * 4);
        }
        __syncthreads();

        // S = Q K^T  (each thread: 4x4)
        float s[4][4];
#pragma unroll
        for (int i = 0; i < 4; i++)
#pragma unroll
            for (int j = 0; j < 4; j++) s[i][j] = 0.f;

#pragma unroll 8
        for (int dd = 0; dd < HD; dd++) {
            const float4 kf = *(const float4*)&Kt[dd][tx * 4];
            const float kfa[4] = {kf.x, kf.y, kf.z, kf.w};
#pragma unroll
            for (int i = 0; i < 4; i++) {
                float qv = Qs[ty * 4 + i][dd];
#pragma unroll
                for (int j = 0; j < 4; j++)
                    s[i][j] = fmaf(qv, kfa[j], s[i][j]);
            }
        }

        // scale + positional bias + online softmax (row stats across width-16 group)
#pragma unroll
        for (int i = 0; i < 4; i++) {
            float4 pv = *(const float4*)(pb + (size_t)(ty * 4 + i) * LS + j0 + tx * 4);
            s[i][0] = fmaf(s[i][0], ATT_SCALE, pv.x);
            s[i][1] = fmaf(s[i][1], ATT_SCALE, pv.y);
            s[i][2] = fmaf(s[i][2], ATT_SCALE, pv.z);
            s[i][3] = fmaf(s[i][3], ATT_SCALE, pv.w);

            float rm = fmaxf(fmaxf(s[i][0], s[i][1]), fmaxf(s[i][2], s[i][3]));
#pragma unroll
            for (int off = 8; off; off >>= 1)
                rm = fmaxf(rm, __shfl_xor_sync(0xffffffffu, rm, off, 16));

            float mnew  = fmaxf(mi[i], rm);
            float alpha = __expf(mi[i] - mnew);
            mi[i] = mnew;

            s[i][0] = __expf(s[i][0] - mnew);
            s[i][1] = __expf(s[i][1] - mnew);
            s[i][2] = __expf(s[i][2] - mnew);
            s[i][3] = __expf(s[i][3] - mnew);
            float rs = (s[i][0] + s[i][1]) + (s[i][2] + s[i][3]);
#pragma unroll
            for (int off = 8; off; off >>= 1)
                rs += __shfl_xor_sync(0xffffffffu, rs, off, 16);

            li[i] = li[i] * alpha + rs;
#pragma unroll
            for (int j = 0; j < 4; j++) o[i][j] *= alpha;
        }

        __syncthreads();  // all S-phase reads of Kt are done
        // Store P into the Kt buffer as P[q][k]
#pragma unroll
        for (int i = 0; i < 4; i++)
#pragma unroll
            for (int j = 0; j < 4; j++)
                Kt[ty * 4 + i][tx * 4 + j] = s[i][j];
        __syncthreads();

        // O += P @ V
#pragma unroll 8
        for (int k = 0; k < 64; k++) {
            const float4 vf = *(const float4*)&Vs[k][tx * 4];
            const float vfa[4] = {vf.x, vf.y, vf.z, vf.w};
#pragma unroll
            for (int i = 0; i < 4; i++) {
                float pvv = Kt[ty * 4 + i][k];
#pragma unroll
                for (int j = 0; j < 4; j++)
                    o[i][j] = fmaf(pvv, vfa[j], o[i][j]);
            }
        }
    }

    // Normalize and write [B,L,C]
#pragma unroll
    for (int i = 0; i < 4; i++) {
        float inv = 1.0f / li[i];
        int q = q0 + ty * 4 + i;
        float4 v = make_float4(o[i][0] * inv, o[i][1] * inv, o[i][2] * inv, o[i][3] * inv);
        *(float4*)(g_o + ((size_t)b * LS + q) * CD + h * HD + tx * 4) = v;
    }
}

// ---------------------------------------------------------------------------
// Output projection: out[m,n] = bp[n] + sum_k g_o[m,k] * Wp[n,k]
// Same tiling as qkv_kernel.
// ---------------------------------------------------------------------------
__global__ __launch_bounds__(256) void proj_kernel(
    const float* __restrict__ Wp,
    const float* __restrict__ bp,
    float* __restrict__ out)
{
    __shared__ float As[16][128];
    __shared__ float Bs[16][64];

    const int tid = threadIdx.x;
    const int m0 = blockIdx.y * 128;
    const int n0 = blockIdx.x * 64;

    const int ar = tid >> 2;
    const int ac = (tid & 3) << 2;
    const int ty = tid >> 4;
    const int tx = tid & 15;

    const int m1 = m0 + ar;
    const int m2 = m0 + ar + 64;

    float acc[8][4];
#pragma unroll
    for (int i = 0; i < 8; i++)
#pragma unroll
        for (int j = 0; j < 4; j++) acc[i][j] = 0.f;

    for (int k0 = 0; k0 < CD; k0 += 16) {
        float4 a0 = *(const float4*)(g_o + (size_t)m1 * CD + k0 + ac);
        float4 a1 = *(const float4*)(g_o + (size_t)m2 * CD + k0 + ac);
        float4 b0 = *(const float4*)(Wp + (size_t)(n0 + ar) * CD + k0 + ac);

        As[ac + 0][ar] = a0.x; As[ac + 1][ar] = a0.y;
        As[ac + 2][ar] = a0.z; As[ac + 3][ar] = a0.w;
        As[ac + 0][ar + 64] = a1.x; As[ac + 1][ar + 64] = a1.y;
        As[ac + 2][ar + 64] = a1.z; As[ac + 3][ar + 64] = a1.w;
        Bs[ac + 0][ar] = b0.x; Bs[ac + 1][ar] = b0.y;
        Bs[ac + 2][ar] = b0.z; Bs[ac + 3][ar] = b0.w;
        __syncthreads();

#pragma unroll
        for (int kk = 0; kk < 16; kk++) {
            float af[8], bf[4];
            *(float4*)(af)     = *(const float4*)&As[kk][ty * 8];
            *(float4*)(af + 4) = *(const float4*)&As[kk][ty * 8 + 4];
            *(float4*)(bf)     = *(const float4*)&Bs[kk][tx * 4];
#pragma unroll
            for (int i = 0; i < 8; i++)
#pragma unroll
                for (int j = 0; j < 4; j++)
                    acc[i][j] = fmaf(af[i], bf[j], acc[i][j]);
        }
        __syncthreads();
    }

    float4 bias = *(const float4*)(bp + n0 + tx * 4);
#pragma unroll
    for (int i = 0; i < 8; i++) {
        int m = m0 + ty * 8 + i;
        float4 v = make_float4(acc[i][0] + bias.x, acc[i][1] + bias.y,
                               acc[i][2] + bias.z, acc[i][3] + bias.w);
        *(float4*)(out + (size_t)m * CD + n0 + tx * 4) = v;
    }
}

// ---------------------------------------------------------------------------
extern "C" void kernel_launch(void* const* d_in, const int* in_sizes, int n_in,
                              void* d_out, int out_size)
{
    const float* x    = (const float*)d_in[0];
    const float* qape = (const float*)d_in[1];
    const float* kape = (const float*)d_in[2];
    const float* pos  = (const float*)d_in[3];
    const float* Wq   = (const float*)d_in[4];
    const float* Wk   = (const float*)d_in[5];
    const float* Wv   = (const float*)d_in[6];
    const float* Wp   = (const float*)d_in[7];
    const float* bp   = (const float*)d_in[8];
    float* out = (float*)d_out;

    dim3 gemm_grid(CD / 64, ML / 128, 3);   // 12 x 32 x 3
    qkv_kernel<<<gemm_grid, 256>>>(x, qape, kape, Wq, Wk, Wv);

    dim3 attn_grid(LS / 64, BATCH * NH);    // 16 x 48
    attn_kernel<<<attn_grid, 256>>>(pos);

    dim3 proj_grid(CD / 64, ML / 128, 1);   // 12 x 32
    proj_kernel<<<proj_grid, 256>>>(Wp, bp, out);
}

// round 2
// speedup vs baseline: 2.0130x; 2.0130x over previous
#include <cuda_runtime.h>
#include <cstdint>

#define NH 12
#define HD 64
#define CD 768
#define LS 1024
#define BATCH 4
#define ML (BATCH*LS)
#define ATT_SCALE 0.125f

// Scratch
__device__ float g_q[ML*CD];   // [B,H,L,D]
__device__ float g_k[ML*CD];   // [B,H,L,D]
__device__ float g_v[ML*CD];   // [B,H,L,D]
__device__ float g_o[ML*CD];   // [B,L,C]

__device__ __forceinline__ uint32_t f2tf(float x) {
    uint32_t r;
    asm("cvt.rna.tf32.f32 %0, %1;" : "=r"(r) : "f"(x));
    return r;
}
__device__ __forceinline__ float tf2f(uint32_t x) { return __uint_as_float(x); }

__device__ __forceinline__ void mma_tf32(float c[4],
    uint32_t a0, uint32_t a1, uint32_t a2, uint32_t a3,
    uint32_t b0, uint32_t b1)
{
    asm volatile(
        "mma.sync.aligned.m16n8k8.row.col.f32.tf32.tf32.f32 "
        "{%0,%1,%2,%3}, {%4,%5,%6,%7}, {%8,%9}, {%0,%1,%2,%3};\n"
        : "+f"(c[0]), "+f"(c[1]), "+f"(c[2]), "+f"(c[3])
        : "r"(a0), "r"(a1), "r"(a2), "r"(a3), "r"(b0), "r"(b1));
}

// ---------------------------------------------------------------------------
// GEMM core: C[m,n] = sum_k A[m,k] * W[n,k]  (NT), tf32 MMA, fp32 accum.
// Block 128x128, BK=16, 256 threads (8 warps in 2x4), warp tile 64x32.
// Smem stride 20 (bank-conflict-free for both A and B fragment reads).
// ---------------------------------------------------------------------------
#define GSTRIDE 20

__global__ __launch_bounds__(256) void qkv_kernel(
    const float* __restrict__ x,
    const float* __restrict__ qape,
    const float* __restrict__ kape,
    const float* __restrict__ Wq,
    const float* __restrict__ Wk,
    const float* __restrict__ Wv)
{
    __shared__ float As[2][128][GSTRIDE];
    __shared__ float Bs[2][128][GSTRIDE];

    const int which = blockIdx.z;
    const float* ape = (which == 0) ? qape : (which == 1) ? kape : nullptr;
    const float* W   = (which == 0) ? Wq   : (which == 1) ? Wk   : Wv;
    float* out       = (which == 0) ? g_q  : (which == 1) ? g_k  : g_v;

    const int tid  = threadIdx.x;
    const int lane = tid & 31;
    const int warp = tid >> 5;
    const int gid  = lane >> 2;
    const int tig  = lane & 3;
    const int wm   = warp >> 2;   // 0..1
    const int wn   = warp & 3;    // 0..3

    const int m0 = blockIdx.y * 128;
    const int n0 = blockIdx.x * 128;

    const int lr = tid >> 1;          // 0..127
    const int lc = (tid & 1) << 3;    // 0 or 8

    const float* arow = x + (size_t)(m0 + lr) * CD + lc;
    const float* prow = ape ? ape + (size_t)((m0 + lr) & (LS - 1)) * CD + lc : nullptr;
    const float* brow = W + (size_t)(n0 + lr) * CD + lc;

    float c[4][4][4];
#pragma unroll
    for (int i = 0; i < 4; i++)
#pragma unroll
        for (int j = 0; j < 4; j++)
#pragma unroll
            for (int v = 0; v < 4; v++) c[i][j][v] = 0.f;

    float ar[8], br[8];
    // initial tile
    {
        float4 a0 = *(const float4*)(arow);
        float4 a1 = *(const float4*)(arow + 4);
        if (prow) {
            float4 p0 = *(const float4*)(prow);
            float4 p1 = *(const float4*)(prow + 4);
            a0.x += p0.x; a0.y += p0.y; a0.z += p0.z; a0.w += p0.w;
            a1.x += p1.x; a1.y += p1.y; a1.z += p1.z; a1.w += p1.w;
        }
        float4 b0 = *(const float4*)(brow);
        float4 b1 = *(const float4*)(brow + 4);
        ar[0]=a0.x; ar[1]=a0.y; ar[2]=a0.z; ar[3]=a0.w;
        ar[4]=a1.x; ar[5]=a1.y; ar[6]=a1.z; ar[7]=a1.w;
        br[0]=b0.x; br[1]=b0.y; br[2]=b0.z; br[3]=b0.w;
        br[4]=b1.x; br[5]=b1.y; br[6]=b1.z; br[7]=b1.w;
#pragma unroll
        for (int u = 0; u < 8; u++) {
            As[0][lr][lc + u] = tf2f(f2tf(ar[u]));
            Bs[0][lr][lc + u] = tf2f(f2tf(br[u]));
        }
    }
    __syncthreads();

    int st = 0;
    const int NIT = CD / 16;  // 48
    for (int it = 0; it < NIT; ++it) {
        if (it + 1 < NIT) {
            int k0 = (it + 1) * 16;
            float4 a0 = *(const float4*)(arow + k0);
            float4 a1 = *(const float4*)(arow + k0 + 4);
            if (prow) {
                float4 p0 = *(const float4*)(prow + k0);
                float4 p1 = *(const float4*)(prow + k0 + 4);
                a0.x += p0.x; a0.y += p0.y; a0.z += p0.z; a0.w += p0.w;
                a1.x += p1.x; a1.y += p1.y; a1.z += p1.z; a1.w += p1.w;
            }
            float4 b0 = *(const float4*)(brow + k0);
            float4 b1 = *(const float4*)(brow + k0 + 4);
            ar[0]=a0.x; ar[1]=a0.y; ar[2]=a0.z; ar[3]=a0.w;
            ar[4]=a1.x; ar[5]=a1.y; ar[6]=a1.z; ar[7]=a1.w;
            br[0]=b0.x; br[1]=b0.y; br[2]=b0.z; br[3]=b0.w;
            br[4]=b1.x; br[5]=b1.y; br[6]=b1.z; br[7]=b1.w;
        }
#pragma unroll
        for (int kk = 0; kk < 16; kk += 8) {
            uint32_t af[4][4], bf[4][2];
#pragma unroll
            for (int ma = 0; ma < 4; ma++) {
                int row = wm * 64 + ma * 16 + gid;
                af[ma][0] = __float_as_uint(As[st][row][kk + tig]);
                af[ma][1] = __float_as_uint(As[st][row + 8][kk + tig]);
                af[ma][2] = __float_as_uint(As[st][row][kk + 4 + tig]);
                af[ma][3] = __float_as_uint(As[st][row + 8][kk + 4 + tig]);
            }
#pragma unroll
            for (int nb = 0; nb < 4; nb++) {
                int n = wn * 32 + nb * 8 + gid;
                bf[nb][0] = __float_as_uint(Bs[st][n][kk + tig]);
                bf[nb][1] = __float_as_uint(Bs[st][n][kk + 4 + tig]);
            }
#pragma unroll
            for (int ma = 0; ma < 4; ma++)
#pragma unroll
                for (int nb = 0; nb < 4; nb++)
                    mma_tf32(c[ma][nb], af[ma][0], af[ma][1], af[ma][2], af[ma][3],
                             bf[nb][0], bf[nb][1]);
        }
        if (it + 1 < NIT) {
#pragma unroll
            for (int u = 0; u < 8; u++) {
                As[st ^ 1][lr][lc + u] = tf2f(f2tf(ar[u]));
                Bs[st ^ 1][lr][lc + u] = tf2f(f2tf(br[u]));
            }
            __syncthreads();
            st ^= 1;
        }
    }

    // epilogue -> [B,H,L,D]
#pragma unroll
    for (int ma = 0; ma < 4; ma++) {
        int row0 = m0 + wm * 64 + ma * 16 + gid;
        int row1 = row0 + 8;
        int b0i = row0 >> 10, l0 = row0 & (LS - 1);
        int b1i = row1 >> 10, l1 = row1 & (LS - 1);
#pragma unroll
        for (int nb = 0; nb < 4; nb++) {
            int n = n0 + wn * 32 + nb * 8 + 2 * tig;
            int h = n >> 6, d = n & 63;
            *(float2*)(out + ((size_t)((b0i * NH + h) * LS + l0)) * HD + d) =
                make_float2(c[ma][nb][0], c[ma][nb][1]);
            *(float2*)(out + ((size_t)((b1i * NH + h) * LS + l1)) * HD + d) =
                make_float2(c[ma][nb][2], c[ma][nb][3]);
        }
    }
}

// ---------------------------------------------------------------------------
// Attention: per (b,h), 64-query block, 4 warps (warp owns 16 q-rows),
// 32-key tiles, tf32 MMA for QK^T and PV, online softmax on fragments.
// ---------------------------------------------------------------------------
__global__ __launch_bounds__(128) void attn_kernel(const float* __restrict__ pos)
{
    __shared__ float Qs[64][72];   // reused as Ps[64][36] after Q frags built
    __shared__ float Ks[32][68];
    __shared__ float Vs[32][72];

    const int tid  = threadIdx.x;
    const int lane = tid & 31;
    const int warp = tid >> 5;
    const int gid  = lane >> 2;
    const int tig  = lane & 3;

    const int bh = blockIdx.y;
    const int b  = bh / NH;
    const int h  = bh - b * NH;
    const int q0 = blockIdx.x * 64;

    const float* qb = g_q + ((size_t)bh * LS + q0) * HD;
    const float* kb = g_k + (size_t)bh * LS * HD;
    const float* vb = g_v + (size_t)bh * LS * HD;

    // load Q tile (coalesced), tf32-convert
    {
        int row = tid >> 1;
        int cs  = (tid & 1) * 32;
#pragma unroll
        for (int u = 0; u < 8; u++) {
            float4 v = *(const float4*)(qb + (size_t)row * HD + cs + u * 4);
            Qs[row][cs + u * 4 + 0] = tf2f(f2tf(v.x));
            Qs[row][cs + u * 4 + 1] = tf2f(f2tf(v.y));
            Qs[row][cs + u * 4 + 2] = tf2f(f2tf(v.z));
            Qs[row][cs + u * 4 + 3] = tf2f(f2tf(v.w));
        }
    }
    __syncthreads();

    const int r = warp * 16 + gid;    // this thread's first q row within tile
    uint32_t qa[8][4];
#pragma unroll
    for (int ks = 0; ks < 8; ks++) {
        int k = ks * 8;
        qa[ks][0] = __float_as_uint(Qs[r][k + tig]);
        qa[ks][1] = __float_as_uint(Qs[r + 8][k + tig]);
        qa[ks][2] = __float_as_uint(Qs[r][k + 4 + tig]);
        qa[ks][3] = __float_as_uint(Qs[r + 8][k + 4 + tig]);
    }
    float* Ps = &Qs[0][0];   // [64][36] view

    float o[8][4];
#pragma unroll
    for (int nb = 0; nb < 8; nb++)
#pragma unroll
        for (int v = 0; v < 4; v++) o[nb][v] = 0.f;
    float mi[2] = {-1e30f, -1e30f};
    float li[2] = {0.f, 0.f};

    const int krow = tid >> 2;          // 0..31 loader row for K/V
    const int kcs  = (tid & 3) * 16;    // col segment

    for (int j0 = 0; j0 < LS; j0 += 32) {
        __syncthreads();   // previous-iter Ks/Vs reads done; Qs frags built (iter 0)
#pragma unroll
        for (int u = 0; u < 4; u++) {
            float4 kv = *(const float4*)(kb + (size_t)(j0 + krow) * HD + kcs + u * 4);
            Ks[krow][kcs + u * 4 + 0] = tf2f(f2tf(kv.x));
            Ks[krow][kcs + u * 4 + 1] = tf2f(f2tf(kv.y));
            Ks[krow][kcs + u * 4 + 2] = tf2f(f2tf(kv.z));
            Ks[krow][kcs + u * 4 + 3] = tf2f(f2tf(kv.w));
            float4 vv = *(const float4*)(vb + (size_t)(j0 + krow) * HD + kcs + u * 4);
            Vs[krow][kcs + u * 4 + 0] = tf2f(f2tf(vv.x));
            Vs[krow][kcs + u * 4 + 1] = tf2f(f2tf(vv.y));
            Vs[krow][kcs + u * 4 + 2] = tf2f(f2tf(vv.z));
            Vs[krow][kcs + u * 4 + 3] = tf2f(f2tf(vv.w));
        }
        __syncthreads();

        // S = Q K^T   (4 n-atoms = 32 keys)
        float s[4][4];
#pragma unroll
        for (int nb = 0; nb < 4; nb++)
#pragma unroll
            for (int v = 0; v < 4; v++) s[nb][v] = 0.f;
#pragma unroll
        for (int ks = 0; ks < 8; ks++) {
            int k = ks * 8;
#pragma unroll
            for (int nb = 0; nb < 4; nb++) {
                uint32_t b0 = __float_as_uint(Ks[nb * 8 + gid][k + tig]);
                uint32_t b1 = __float_as_uint(Ks[nb * 8 + gid][k + 4 + tig]);
                mma_tf32(s[nb], qa[ks][0], qa[ks][1], qa[ks][2], qa[ks][3], b0, b1);
            }
        }

        // scale + pos + online softmax per row-pair
#pragma unroll
        for (int rp = 0; rp < 2; rp++) {
            int row = r + rp * 8;
            const float* pb = pos + ((size_t)(h * LS + q0 + row)) * LS + j0 + 2 * tig;
            float rm = -1e30f;
#pragma unroll
            for (int nb = 0; nb < 4; nb++) {
                float2 pv = *(const float2*)(pb + nb * 8);
                float v0 = fmaf(s[nb][2 * rp],     ATT_SCALE, pv.x);
                float v1 = fmaf(s[nb][2 * rp + 1], ATT_SCALE, pv.y);
                s[nb][2 * rp]     = v0;
                s[nb][2 * rp + 1] = v1;
                rm = fmaxf(rm, fmaxf(v0, v1));
            }
            rm = fmaxf(rm, __shfl_xor_sync(0xffffffffu, rm, 1));
            rm = fmaxf(rm, __shfl_xor_sync(0xffffffffu, rm, 2));
            float mnew  = fmaxf(mi[rp], rm);
            float alpha = __expf(mi[rp] - mnew);
            mi[rp] = mnew;
            float rs = 0.f;
#pragma unroll
            for (int nb = 0; nb < 4; nb++) {
                float e0 = __expf(s[nb][2 * rp] - mnew);
                float e1 = __expf(s[nb][2 * rp + 1] - mnew);
                s[nb][2 * rp]     = e0;
                s[nb][2 * rp + 1] = e1;
                rs += e0 + e1;
            }
            rs += __shfl_xor_sync(0xffffffffu, rs, 1);
            rs += __shfl_xor_sync(0xffffffffu, rs, 2);
            li[rp] = li[rp] * alpha + rs;
#pragma unroll
            for (int nb = 0; nb < 8; nb++) {
                o[nb][2 * rp]     *= alpha;
                o[nb][2 * rp + 1] *= alpha;
            }
        }

        // store P (tf32) into Ps[64][36] — warp-private rows
#pragma unroll
        for (int nb = 0; nb < 4; nb++) {
            int col = nb * 8 + 2 * tig;
            Ps[r * 36 + col]           = tf2f(f2tf(s[nb][0]));
            Ps[r * 36 + col + 1]       = tf2f(f2tf(s[nb][1]));
            Ps[(r + 8) * 36 + col]     = tf2f(f2tf(s[nb][2]));
            Ps[(r + 8) * 36 + col + 1] = tf2f(f2tf(s[nb][3]));
        }
        __syncwarp();

        // O += P @ V   (4 k-steps over 32 keys, 8 n-atoms over d=64)
#pragma unroll
        for (int ks = 0; ks < 4; ks++) {
            int k = ks * 8;
            uint32_t p0 = __float_as_uint(Ps[r * 36 + k + tig]);
            uint32_t p1 = __float_as_uint(Ps[(r + 8) * 36 + k + tig]);
            uint32_t p2 = __float_as_uint(Ps[r * 36 + k + 4 + tig]);
            uint32_t p3 = __float_as_uint(Ps[(r + 8) * 36 + k + 4 + tig]);
#pragma unroll
            for (int nb = 0; nb < 8; nb++) {
                uint32_t b0 = __float_as_uint(Vs[k + tig][nb * 8 + gid]);
                uint32_t b1 = __float_as_uint(Vs[k + 4 + tig][nb * 8 + gid]);
                mma_tf32(o[nb], p0, p1, p2, p3, b0, b1);
            }
        }
    }

    // normalize, write g_o[B,L,C]
    float inv0 = 1.0f / li[0];
    float inv1 = 1.0f / li[1];
#pragma unroll
    for (int nb = 0; nb < 8; nb++) {
        int d = nb * 8 + 2 * tig;
        *(float2*)(g_o + ((size_t)(b * LS + q0 + r)) * CD + h * HD + d) =
            make_float2(o[nb][0] * inv0, o[nb][1] * inv0);
        *(float2*)(g_o + ((size_t)(b * LS + q0 + r + 8)) * CD + h * HD + d) =
            make_float2(o[nb][2] * inv1, o[nb][3] * inv1);
    }
}

// ---------------------------------------------------------------------------
// Output projection: out[m,n] = bp[n] + sum_k g_o[m,k]*Wp[n,k]
// ---------------------------------------------------------------------------
__global__ __launch_bounds__(256) void proj_kernel(
    const float* __restrict__ Wp,
    const float* __restrict__ bp,
    float* __restrict__ out)
{
    __shared__ float As[2][128][GSTRIDE];
    __shared__ float Bs[2][128][GSTRIDE];

    const int tid  = threadIdx.x;
    const int lane = tid & 31;
    const int warp = tid >> 5;
    const int gid  = lane >> 2;
    const int tig  = lane & 3;
    const int wm   = warp >> 2;
    const int wn   = warp & 3;

    const int m0 = blockIdx.y * 128;
    const int n0 = blockIdx.x * 128;
    const int lr = tid >> 1;
    const int lc = (tid & 1) << 3;

    const float* arow = g_o + (size_t)(m0 + lr) * CD + lc;
    const float* brow = Wp  + (size_t)(n0 + lr) * CD + lc;

    float c[4][4][4];
#pragma unroll
    for (int i = 0; i < 4; i++)
#pragma unroll
        for (int j = 0; j < 4; j++)
#pragma unroll
            for (int v = 0; v < 4; v++) c[i][j][v] = 0.f;

    float ar[8], br[8];
    {
        float4 a0 = *(const float4*)(arow);
        float4 a1 = *(const float4*)(arow + 4);
        float4 b0 = *(const float4*)(brow);
        float4 b1 = *(const float4*)(brow + 4);
        ar[0]=a0.x; ar[1]=a0.y; ar[2]=a0.z; ar[3]=a0.w;
        ar[4]=a1.x; ar[5]=a1.y; ar[6]=a1.z; ar[7]=a1.w;
        br[0]=b0.x; br[1]=b0.y; br[2]=b0.z; br[3]=b0.w;
        br[4]=b1.x; br[5]=b1.y; br[6]=b1.z; br[7]=b1.w;
#pragma unroll
        for (int u = 0; u < 8; u++) {
            As[0][lr][lc + u] = tf2f(f2tf(ar[u]));
            Bs[0][lr][lc + u] = tf2f(f2tf(br[u]));
        }
    }
    __syncthreads();

    int st = 0;
    const int NIT = CD / 16;
    for (int it = 0; it < NIT; ++it) {
        if (it + 1 < NIT) {
            int k0 = (it + 1) * 16;
            float4 a0 = *(const float4*)(arow + k0);
            float4 a1 = *(const float4*)(arow + k0 + 4);
            float4 b0 = *(const float4*)(brow + k0);
            float4 b1 = *(const float4*)(brow + k0 + 4);
            ar[0]=a0.x; ar[1]=a0.y; ar[2]=a0.z; ar[3]=a0.w;
            ar[4]=a1.x; ar[5]=a1.y; ar[6]=a1.z; ar[7]=a1.w;
            br[0]=b0.x; br[1]=b0.y; br[2]=b0.z; br[3]=b0.w;
            br[4]=b1.x; br[5]=b1.y; br[6]=b1.z; br[7]=b1.w;
        }
#pragma unroll
        for (int kk = 0; kk < 16; kk += 8) {
            uint32_t af[4][4], bf[4][2];
#pragma unroll
            for (int ma = 0; ma < 4; ma++) {
                int row = wm * 64 + ma * 16 + gid;
                af[ma][0] = __float_as_uint(As[st][row][kk + tig]);
                af[ma][1] = __float_as_uint(As[st][row + 8][kk + tig]);
                af[ma][2] = __float_as_uint(As[st][row][kk + 4 + tig]);
                af[ma][3] = __float_as_uint(As[st][row + 8][kk + 4 + tig]);
            }
#pragma unroll
            for (int nb = 0; nb < 4; nb++) {
                int n = wn * 32 + nb * 8 + gid;
                bf[nb][0] = __float_as_uint(Bs[st][n][kk + tig]);
                bf[nb][1] = __float_as_uint(Bs[st][n][kk + 4 + tig]);
            }
#pragma unroll
            for (int ma = 0; ma < 4; ma++)
#pragma unroll
                for (int nb = 0; nb < 4; nb++)
                    mma_tf32(c[ma][nb], af[ma][0], af[ma][1], af[ma][2], af[ma][3],
                             bf[nb][0], bf[nb][1]);
        }
        if (it + 1 < NIT) {
#pragma unroll
            for (int u = 0; u < 8; u++) {
                As[st ^ 1][lr][lc + u] = tf2f(f2tf(ar[u]));
                Bs[st ^ 1][lr][lc + u] = tf2f(f2tf(br[u]));
            }
            __syncthreads();
            st ^= 1;
        }
    }

#pragma unroll
    for (int ma = 0; ma < 4; ma++) {
        int row0 = m0 + wm * 64 + ma * 16 + gid;
        int row1 = row0 + 8;
#pragma unroll
        for (int nb = 0; nb < 4; nb++) {
            int n = n0 + wn * 32 + nb * 8 + 2 * tig;
            float2 bias = *(const float2*)(bp + n);
            *(float2*)(out + (size_t)row0 * CD + n) =
                make_float2(c[ma][nb][0] + bias.x, c[ma][nb][1] + bias.y);
            *(float2*)(out + (size_t)row1 * CD + n) =
                make_float2(c[ma][nb][2] + bias.x, c[ma][nb][3] + bias.y);
        }
    }
}

// ---------------------------------------------------------------------------
extern "C" void kernel_launch(void* const* d_in, const int* in_sizes, int n_in,
                              void* d_out, int out_size)
{
    const float* x    = (const float*)d_in[0];
    const float* qape = (const float*)d_in[1];
    const float* kape = (const float*)d_in[2];
    const float* pos  = (const float*)d_in[3];
    const float* Wq   = (const float*)d_in[4];
    const float* Wk   = (const float*)d_in[5];
    const float* Wv   = (const float*)d_in[6];
    const float* Wp   = (const float*)d_in[7];
    const float* bp   = (const float*)d_in[8];
    float* out = (float*)d_out;

    dim3 gemm_grid(CD / 128, ML / 128, 3);   // 6 x 32 x 3
    qkv_kernel<<<gemm_grid, 256>>>(x, qape, kape, Wq, Wk, Wv);

    dim3 attn_grid(LS / 64, BATCH * NH);     // 16 x 48
    attn_kernel<<<attn_grid, 128>>>(pos);

    dim3 proj_grid(CD / 128, ML / 128, 1);   // 6 x 32
    proj_kernel<<<proj_grid, 256>>>(Wp, bp, out);
}